// round 1
// baseline (speedup 1.0000x reference)
#include <cuda_runtime.h>
#include <cstdint>

// Problem constants
constexpr int B_  = 32;
constexpr int T_  = 1024;
constexpr int F_  = 512;
constexpr int H_  = 512;
constexpr int G4H = 2048;   // 4*H

// Recurrence launch shape
#define NB 128   // blocks (<= 148 SMs -> all co-resident, custom grid barrier is safe)
#define NT 128   // threads per block

// ---------------- device scratch (no mallocs allowed) ----------------
__device__ float g_z0t[(size_t)T_ * G4H * B_];   // [t][col][b]  (256 MB)
__device__ float g_hT[2][H_ * B_];               // ping-pong h, transposed [k][b]
__device__ unsigned g_count;
__device__ volatile unsigned g_sense;

// ---------------- init: transpose h0 into hT[0], reset barrier ----------------
__global__ void lstm_init(const float* __restrict__ h0) {
    int i = blockIdx.x * blockDim.x + threadIdx.x;
    if (i < H_ * B_) {
        int b = i / H_;
        int k = i - b * H_;
        g_hT[0][k * B_ + b] = h0[i];
    }
    if (i == 0) { g_count = 0; g_sense = 0; }
}

// ---------------- GEMM: z0t[t][col][b] = x[b,t,:] @ Wi[:,col] + bias[col] ----------------
// M = B*T = 32768 (rows of x, row = b*1024 + t), K = 512, N = 2048.
// 64x64 tile, BK=16, 256 threads, 4x4 register micro-tile.
__global__ void __launch_bounds__(256) gemm_xwi(const float* __restrict__ x,
                                                const float* __restrict__ Wi,
                                                const float* __restrict__ bias) {
    __shared__ float As[16][64];
    __shared__ float Bs[16][64];
    const int tid = threadIdx.x;
    const int tm = tid >> 4;        // 0..15
    const int tn = tid & 15;        // 0..15
    const int row0 = blockIdx.y * 64;
    const int col0 = blockIdx.x * 64;

    float acc[4][4] = {};

    const int ar  = tid >> 2;        // 0..63  (A row within tile)
    const int akq = (tid & 3) * 4;   // 0,4,8,12 (k offset)
    const int br  = tid >> 4;        // 0..15  (B k-row within tile)
    const int bnq = (tid & 15) * 4;  // col offset

    for (int kt = 0; kt < F_; kt += 16) {
        float4 av = *(const float4*)&x[(size_t)(row0 + ar) * F_ + kt + akq];
        As[akq + 0][ar] = av.x;
        As[akq + 1][ar] = av.y;
        As[akq + 2][ar] = av.z;
        As[akq + 3][ar] = av.w;
        *(float4*)&Bs[br][bnq] =
            *(const float4*)&Wi[(size_t)(kt + br) * G4H + col0 + bnq];
        __syncthreads();
#pragma unroll
        for (int k = 0; k < 16; k++) {
            float4 a  = *(const float4*)&As[k][tm * 4];
            float4 b4 = *(const float4*)&Bs[k][tn * 4];
            acc[0][0] += a.x * b4.x; acc[0][1] += a.x * b4.y;
            acc[0][2] += a.x * b4.z; acc[0][3] += a.x * b4.w;
            acc[1][0] += a.y * b4.x; acc[1][1] += a.y * b4.y;
            acc[1][2] += a.y * b4.z; acc[1][3] += a.y * b4.w;
            acc[2][0] += a.z * b4.x; acc[2][1] += a.z * b4.y;
            acc[2][2] += a.z * b4.z; acc[2][3] += a.z * b4.w;
            acc[3][0] += a.w * b4.x; acc[3][1] += a.w * b4.y;
            acc[3][2] += a.w * b4.z; acc[3][3] += a.w * b4.w;
        }
        __syncthreads();
    }

#pragma unroll
    for (int i = 0; i < 4; i++) {
        int r  = row0 + tm * 4 + i;
        int t  = r & (T_ - 1);
        int bb = r >> 10;
#pragma unroll
        for (int j = 0; j < 4; j++) {
            int c = col0 + tn * 4 + j;
            g_z0t[((size_t)t * G4H + c) * B_ + bb] = acc[i][j] + bias[c];
        }
    }
}

// ---------------- recurrence: persistent kernel, custom grid barrier ----------------
// Block bx owns h columns [bx*4, bx*4+4). Thread: b = tid&31, nl = tid>>5.
// Each thread computes the 4 gate pre-activations for its (b, ncol) and carries c.
__global__ void __launch_bounds__(NT, 1) lstm_rec(const float* __restrict__ c0,
                                                  const float* __restrict__ Wh,
                                                  float* __restrict__ out) {
    __shared__ float4 Whs[H_ * 4];   // [k][nl] -> (i,f,g,o) weights packed; 32 KB

    const int tid  = threadIdx.x;
    const int b    = tid & 31;
    const int nl   = tid >> 5;                  // 0..3
    const int ncol = blockIdx.x * 4 + nl;       // global h column

    // Stage this block's Wh slice ONCE (reused for all 1024 steps).
    for (int idx = tid; idx < H_ * 4; idx += NT) {
        int k  = idx >> 2;
        int n2 = idx & 3;
        int cb = blockIdx.x * 4 + n2;
        float4 w;
        w.x = Wh[(size_t)k * G4H + 0 * H_ + cb];
        w.y = Wh[(size_t)k * G4H + 1 * H_ + cb];
        w.z = Wh[(size_t)k * G4H + 2 * H_ + cb];
        w.w = Wh[(size_t)k * G4H + 3 * H_ + cb];
        Whs[idx] = w;
    }

    float c = c0[(size_t)b * H_ + ncol];

    float* c_fin = out;
    float* h_fin = out + B_ * H_;
    float* hist  = out + 2 * B_ * H_;           // [b][t][h]

    __syncthreads();

    unsigned ls = 0;
    for (int t = 0; t < T_; t++) {
        const float* __restrict__ hsrc = g_hT[t & 1];
        float* hdst = g_hT[(t + 1) & 1];

        // Prefetch the precomputed input-projection terms (coalesced over b).
        size_t zbase = ((size_t)t * G4H + ncol) * B_ + b;
        float z0 = g_z0t[zbase + (size_t)0 * H_ * B_];
        float z1 = g_z0t[zbase + (size_t)1 * H_ * B_];
        float z2 = g_z0t[zbase + (size_t)2 * H_ * B_];
        float z3 = g_z0t[zbase + (size_t)3 * H_ * B_];

        float a0 = 0.f, a1 = 0.f, a2 = 0.f, a3 = 0.f;
#pragma unroll 8
        for (int k = 0; k < H_; k++) {
            float  hv = hsrc[k * B_ + b];       // coalesced, L1-reused across warps
            float4 w  = Whs[k * 4 + nl];        // broadcast within warp
            a0 += hv * w.x;
            a1 += hv * w.y;
            a2 += hv * w.z;
            a3 += hv * w.w;
        }
        a0 += z0; a1 += z1; a2 += z2; a3 += z3;

        float ig = 1.f / (1.f + __expf(-a0));
        float fg = 1.f / (1.f + __expf(-a1));
        float gg = tanhf(a2);
        float og = 1.f / (1.f + __expf(-a3));
        c = fg * c + ig * gg;
        float h = og * tanhf(c);

        hdst[ncol * B_ + b] = h;                           // coalesced (L2-hot ping-pong)
        hist[((size_t)b * T_ + t) * H_ + ncol] = h;        // output history

        if (t == T_ - 1) {
            c_fin[b * H_ + ncol] = c;
            h_fin[b * H_ + ncol] = h;
        }

        // ---- grid-wide sense-reversal barrier (self-cleaning; T even) ----
        ls ^= 1;
        __threadfence();          // publish h writes (also orders vs. arrive)
        __syncthreads();
        if (tid == 0) {
            unsigned old = atomicAdd(&g_count, 1);
            if (old == NB - 1) {
                atomicExch(&g_count, 0);
                __threadfence();
                g_sense = ls;
            } else {
                while (g_sense != ls) __nanosleep(32);
            }
        }
        __syncthreads();
        __threadfence();          // CCTL.IVALL: invalidate L1 so fresh h is read
    }
}

// ---------------- launch ----------------
extern "C" void kernel_launch(void* const* d_in, const int* in_sizes, int n_in,
                              void* d_out, int out_size) {
    const float* x    = (const float*)d_in[0];
    const float* h0   = (const float*)d_in[1];
    const float* c0   = (const float*)d_in[2];
    const float* Wi   = (const float*)d_in[3];
    const float* Wh   = (const float*)d_in[4];
    const float* bias = (const float*)d_in[5];
    float* out = (float*)d_out;

    lstm_init<<<(H_ * B_ + 255) / 256, 256>>>(h0);

    dim3 ggrid(G4H / 64, (B_ * T_) / 64);
    gemm_xwi<<<ggrid, 256>>>(x, Wi, bias);

    lstm_rec<<<NB, NT>>>(c0, Wh, out);
}

// round 3
// speedup vs baseline: 1.8962x; 1.8962x over previous
#include <cuda_runtime.h>
#include <cstdint>

// Problem constants
constexpr int B_  = 32;
constexpr int T_  = 1024;
constexpr int F_  = 512;
constexpr int H_  = 512;
constexpr int G4H = 2048;   // 4*H

#define NB 128   // recurrence blocks (<=148 SMs -> co-resident, grid barrier safe)
#define NT 128   // threads per block

// ---------------- device scratch ----------------
__device__ float g_z0t[(size_t)T_ * G4H * B_];   // [t][gatecol][b]
__device__ float g_hT[2][H_ * B_];               // ping-pong h, transposed [k][b]
__device__ unsigned g_count;
__device__ volatile unsigned g_sense;

// ---------------- f32x2 helpers (GEMM only this round) ----------------
__device__ __forceinline__ unsigned long long pack2(float x, float y) {
    unsigned long long r;
    asm("mov.b64 %0, {%1, %2};" : "=l"(r) : "f"(x), "f"(y));
    return r;
}
__device__ __forceinline__ unsigned long long fma2(unsigned long long a,
                                                   unsigned long long b,
                                                   unsigned long long c) {
    unsigned long long d;
    asm("fma.rn.f32x2 %0, %1, %2, %3;" : "=l"(d) : "l"(a), "l"(b), "l"(c));
    return d;
}
__device__ __forceinline__ float2 unpack2(unsigned long long v) {
    float2 f;
    asm("mov.b64 {%0, %1}, %2;" : "=f"(f.x), "=f"(f.y) : "l"(v));
    return f;
}

// ---------------- init ----------------
__global__ void lstm_init(const float* __restrict__ h0) {
    int i = blockIdx.x * blockDim.x + threadIdx.x;
    if (i < H_ * B_) {
        int b = i / H_;
        int k = i - b * H_;
        g_hT[0][k * B_ + b] = h0[i];
    }
    if (i == 0) { g_count = 0; g_sense = 0; }
}

// ---------------- GEMM (f32x2): z0t[t][col][b] = x[b,t,:] @ Wi[:,col] + bias ----------------
// M = B*T = 32768, K = 512, N = 2048. 64x64 tile, BK=16, 256 threads, 4x4 micro-tile.
__global__ void __launch_bounds__(256) gemm_xwi(const float* __restrict__ x,
                                                const float* __restrict__ Wi,
                                                const float* __restrict__ bias) {
    __shared__ float As[16][64];
    __shared__ float Bs[16][64];
    const int tid = threadIdx.x;
    const int tm = tid >> 4;
    const int tn = tid & 15;
    const int row0 = blockIdx.y * 64;
    const int col0 = blockIdx.x * 64;

    unsigned long long acc[4][2] = {};   // rows x (col pairs), fp32x2

    const int ar  = tid >> 2;
    const int akq = (tid & 3) * 4;
    const int br  = tid >> 4;
    const int bnq = (tid & 15) * 4;

    for (int kt = 0; kt < F_; kt += 16) {
        float4 av = *(const float4*)&x[(size_t)(row0 + ar) * F_ + kt + akq];
        As[akq + 0][ar] = av.x;
        As[akq + 1][ar] = av.y;
        As[akq + 2][ar] = av.z;
        As[akq + 3][ar] = av.w;
        *(float4*)&Bs[br][bnq] =
            *(const float4*)&Wi[(size_t)(kt + br) * G4H + col0 + bnq];
        __syncthreads();
#pragma unroll
        for (int k = 0; k < 16; k++) {
            float4 a = *(const float4*)&As[k][tm * 4];
            const unsigned long long* bp =
                (const unsigned long long*)&Bs[k][tn * 4];
            unsigned long long b0 = bp[0], b1 = bp[1];
            unsigned long long a0 = pack2(a.x, a.x);
            unsigned long long a1 = pack2(a.y, a.y);
            unsigned long long a2 = pack2(a.z, a.z);
            unsigned long long a3 = pack2(a.w, a.w);
            acc[0][0] = fma2(a0, b0, acc[0][0]); acc[0][1] = fma2(a0, b1, acc[0][1]);
            acc[1][0] = fma2(a1, b0, acc[1][0]); acc[1][1] = fma2(a1, b1, acc[1][1]);
            acc[2][0] = fma2(a2, b0, acc[2][0]); acc[2][1] = fma2(a2, b1, acc[2][1]);
            acc[3][0] = fma2(a3, b0, acc[3][0]); acc[3][1] = fma2(a3, b1, acc[3][1]);
        }
        __syncthreads();
    }

#pragma unroll
    for (int i = 0; i < 4; i++) {
        int r  = row0 + tm * 4 + i;
        int t  = r & (T_ - 1);
        int bb = r >> 10;
#pragma unroll
        for (int j = 0; j < 2; j++) {
            float2 v = unpack2(acc[i][j]);
            int c0c = col0 + tn * 4 + j * 2;
            g_z0t[((size_t)t * G4H + c0c + 0) * B_ + bb] = v.x + bias[c0c + 0];
            g_z0t[((size_t)t * G4H + c0c + 1) * B_ + bb] = v.y + bias[c0c + 1];
        }
    }
}

// ---------------- recurrence ----------------
// Block bx owns h columns [bx*4, bx*4+4). Thread: b = tid&31, nl = tid>>5.
// Dynamic smem: Whs4[H*4] float4 (32KB) | hstage[H*B] float (64KB) = 96KB.
// Round-1 trust base: scalar FFMA, round-1 barrier with full fences; the only
// structural change vs the PASSING round-1 recurrence is staging h into smem
// once per step via __ldcg float4 loads (high MLP, L1-bypass).
__global__ void __launch_bounds__(NT, 1) lstm_rec(const float* __restrict__ c0,
                                                  const float* __restrict__ Wh,
                                                  float* __restrict__ out) {
    extern __shared__ unsigned char dsm[];
    float4* Whs4  = (float4*)dsm;                 // [k*4 + nl] -> (wi,wf,wg,wo)
    float* hstage = (float*)(Whs4 + H_ * 4);      // [k][b]

    const int tid  = threadIdx.x;
    const int b    = tid & 31;
    const int nl   = tid >> 5;                    // 0..3
    const int ncol = blockIdx.x * 4 + nl;

    // Stage this block's Wh slice ONCE (reused for all 1024 steps).
    for (int idx = tid; idx < H_ * 4; idx += NT) {
        int k  = idx >> 2;
        int n2 = idx & 3;
        int cb = blockIdx.x * 4 + n2;
        float4 w;
        w.x = Wh[(size_t)k * G4H + 0 * H_ + cb];
        w.y = Wh[(size_t)k * G4H + 1 * H_ + cb];
        w.z = Wh[(size_t)k * G4H + 2 * H_ + cb];
        w.w = Wh[(size_t)k * G4H + 3 * H_ + cb];
        Whs4[idx] = w;
    }

    float c = c0[(size_t)b * H_ + ncol];

    float* c_fin = out;
    float* h_fin = out + B_ * H_;
    float* hist  = out + 2 * B_ * H_;             // [b][t][h]

    __syncthreads();

    unsigned ls = 0;
    for (int t = 0; t < T_; t++) {
        const float4* __restrict__ hsrc4 = (const float4*)g_hT[t & 1]; // 4096 f4
        float* hdst = g_hT[(t + 1) & 1];
        float4* dst4 = (float4*)hstage;

        // ---- z prefetch first (overlaps with the stage below) ----
        size_t zbase = ((size_t)t * G4H + ncol) * B_ + b;
        float a0 = g_z0t[zbase + (size_t)0 * H_ * B_];
        float a1 = g_z0t[zbase + (size_t)1 * H_ * B_];
        float a2 = g_z0t[zbase + (size_t)2 * H_ * B_];
        float a3 = g_z0t[zbase + (size_t)3 * H_ * B_];

        // ---- stage h (64KB) into smem: 32 float4/thread via ld.global.cg ----
        // Chunks of 8 loads -> 8 STS to expose MLP=8 per thread.
#pragma unroll
        for (int cch = 0; cch < 4; cch++) {
            float4 r0 = __ldcg(&hsrc4[tid + NT * (cch * 8 + 0)]);
            float4 r1 = __ldcg(&hsrc4[tid + NT * (cch * 8 + 1)]);
            float4 r2 = __ldcg(&hsrc4[tid + NT * (cch * 8 + 2)]);
            float4 r3 = __ldcg(&hsrc4[tid + NT * (cch * 8 + 3)]);
            float4 r4 = __ldcg(&hsrc4[tid + NT * (cch * 8 + 4)]);
            float4 r5 = __ldcg(&hsrc4[tid + NT * (cch * 8 + 5)]);
            float4 r6 = __ldcg(&hsrc4[tid + NT * (cch * 8 + 6)]);
            float4 r7 = __ldcg(&hsrc4[tid + NT * (cch * 8 + 7)]);
            dst4[tid + NT * (cch * 8 + 0)] = r0;
            dst4[tid + NT * (cch * 8 + 1)] = r1;
            dst4[tid + NT * (cch * 8 + 2)] = r2;
            dst4[tid + NT * (cch * 8 + 3)] = r3;
            dst4[tid + NT * (cch * 8 + 4)] = r4;
            dst4[tid + NT * (cch * 8 + 5)] = r5;
            dst4[tid + NT * (cch * 8 + 6)] = r6;
            dst4[tid + NT * (cch * 8 + 7)] = r7;
        }
        __syncthreads();

        // ---- gate pre-activations: scalar FFMA (round-1 math) ----
#pragma unroll 8
        for (int k = 0; k < H_; k++) {
            float  hv = hstage[k * B_ + b];       // conflict-free LDS.32
            float4 w  = Whs4[k * 4 + nl];         // warp-broadcast LDS.128
            a0 += hv * w.x;
            a1 += hv * w.y;
            a2 += hv * w.z;
            a3 += hv * w.w;
        }

        float ig = 1.f / (1.f + __expf(-a0));
        float fg = 1.f / (1.f + __expf(-a1));
        float gg = tanhf(a2);
        float og = 1.f / (1.f + __expf(-a3));
        c = fg * c + ig * gg;
        float h = og * tanhf(c);

        hdst[ncol * B_ + b] = h;                           // ping-pong publish
        hist[((size_t)b * T_ + t) * H_ + ncol] = h;        // output history

        if (t == T_ - 1) {
            c_fin[b * H_ + ncol] = c;
            h_fin[b * H_ + ncol] = h;
        }

        // ---- grid-wide sense-reversal barrier (EXACT round-1 scheme) ----
        ls ^= 1;
        __threadfence();          // publish h writes before arrive
        __syncthreads();          // all lanes done reading hstage, too
        if (tid == 0) {
            unsigned old = atomicAdd(&g_count, 1);
            if (old == NB - 1) {
                atomicExch(&g_count, 0);
                __threadfence();
                g_sense = ls;
            } else {
                while (g_sense != ls) __nanosleep(32);
            }
        }
        __syncthreads();
        __threadfence();          // consumer-side fence (round-1 trust base)
    }
}

// ---------------- launch ----------------
extern "C" void kernel_launch(void* const* d_in, const int* in_sizes, int n_in,
                              void* d_out, int out_size) {
    const float* x    = (const float*)d_in[0];
    const float* h0   = (const float*)d_in[1];
    const float* c0   = (const float*)d_in[2];
    const float* Wi   = (const float*)d_in[3];
    const float* Wh   = (const float*)d_in[4];
    const float* bias = (const float*)d_in[5];
    float* out = (float*)d_out;

    const int rec_smem = (H_ * 4) * 16 + H_ * B_ * 4;   // 32KB + 64KB = 98304
    cudaFuncSetAttribute(lstm_rec, cudaFuncAttributeMaxDynamicSharedMemorySize,
                         rec_smem);

    lstm_init<<<(H_ * B_ + 255) / 256, 256>>>(h0);

    dim3 ggrid(G4H / 64, (B_ * T_) / 64);
    gemm_xwi<<<ggrid, 256>>>(x, Wi, bias);

    lstm_rec<<<NB, NT, rec_smem>>>(c0, Wh, out);
}

// round 4
// speedup vs baseline: 2.1672x; 1.1429x over previous
#include <cuda_runtime.h>
#include <cstdint>

// Problem constants
constexpr int B_  = 32;
constexpr int T_  = 1024;
constexpr int F_  = 512;
constexpr int H_  = 512;
constexpr int G4H = 2048;   // 4*H

#define NB 128   // recurrence blocks (<=148 SMs -> co-resident, grid barrier safe)
#define NT 128   // threads per block

// ---------------- device scratch ----------------
__device__ float g_z0t[(size_t)T_ * G4H * B_];   // [t][gatecol][b]
__device__ float g_hT[2][H_ * B_];               // ping-pong h, transposed [k][b]
// Monotonic hierarchical barrier state (reset by gemm block (0,0) each call).
__device__ unsigned g_grp[16 * 32];              // 16 counters, 128B apart
__device__ unsigned g_root;
__device__ volatile unsigned g_sense;            // monotonic: step count released

// ---------------- f32x2 helpers ----------------
__device__ __forceinline__ unsigned long long pack2(float x, float y) {
    unsigned long long r;
    asm("mov.b64 %0, {%1, %2};" : "=l"(r) : "f"(x), "f"(y));
    return r;
}
__device__ __forceinline__ unsigned long long fma2(unsigned long long a,
                                                   unsigned long long b,
                                                   unsigned long long c) {
    unsigned long long d;
    asm("fma.rn.f32x2 %0, %1, %2, %3;" : "=l"(d) : "l"(a), "l"(b), "l"(c));
    return d;
}
__device__ __forceinline__ unsigned long long add2(unsigned long long a,
                                                   unsigned long long b) {
    unsigned long long d;
    asm("add.rn.f32x2 %0, %1, %2;" : "=l"(d) : "l"(a), "l"(b));
    return d;
}
__device__ __forceinline__ float2 unpack2(unsigned long long v) {
    float2 f;
    asm("mov.b64 {%0, %1}, %2;" : "=f"(f.x), "=f"(f.y) : "l"(v));
    return f;
}

// ---------------- GEMM (f32x2) + embedded init ----------------
// z0t[t][col][b] = x[b,t,:] @ Wi[:,col] + bias[col]
// M = B*T = 32768, K = 512, N = 2048. 64x64 tile, BK=16, 256 threads.
// Block (0,0) additionally transposes h0 into g_hT[0] and resets the barrier.
__global__ void __launch_bounds__(256) gemm_xwi(const float* __restrict__ x,
                                                const float* __restrict__ Wi,
                                                const float* __restrict__ bias,
                                                const float* __restrict__ h0) {
    __shared__ float As[16][64];
    __shared__ float Bs[16][64];
    const int tid = threadIdx.x;

    if (blockIdx.x == 0 && blockIdx.y == 0) {
        for (int i = tid; i < H_ * B_; i += 256) {
            int b = i / H_;
            int k = i - b * H_;
            g_hT[0][k * B_ + b] = h0[i];
        }
        if (tid < 16) g_grp[tid * 32] = 0;
        if (tid == 0) { g_root = 0; g_sense = 0; }
    }

    const int tm = tid >> 4;
    const int tn = tid & 15;
    const int row0 = blockIdx.y * 64;
    const int col0 = blockIdx.x * 64;

    unsigned long long acc[4][2] = {};

    const int ar  = tid >> 2;
    const int akq = (tid & 3) * 4;
    const int br  = tid >> 4;
    const int bnq = (tid & 15) * 4;

    for (int kt = 0; kt < F_; kt += 16) {
        float4 av = *(const float4*)&x[(size_t)(row0 + ar) * F_ + kt + akq];
        As[akq + 0][ar] = av.x;
        As[akq + 1][ar] = av.y;
        As[akq + 2][ar] = av.z;
        As[akq + 3][ar] = av.w;
        *(float4*)&Bs[br][bnq] =
            *(const float4*)&Wi[(size_t)(kt + br) * G4H + col0 + bnq];
        __syncthreads();
#pragma unroll
        for (int k = 0; k < 16; k++) {
            float4 a = *(const float4*)&As[k][tm * 4];
            const unsigned long long* bp =
                (const unsigned long long*)&Bs[k][tn * 4];
            unsigned long long b0 = bp[0], b1 = bp[1];
            unsigned long long a0 = pack2(a.x, a.x);
            unsigned long long a1 = pack2(a.y, a.y);
            unsigned long long a2 = pack2(a.z, a.z);
            unsigned long long a3 = pack2(a.w, a.w);
            acc[0][0] = fma2(a0, b0, acc[0][0]); acc[0][1] = fma2(a0, b1, acc[0][1]);
            acc[1][0] = fma2(a1, b0, acc[1][0]); acc[1][1] = fma2(a1, b1, acc[1][1]);
            acc[2][0] = fma2(a2, b0, acc[2][0]); acc[2][1] = fma2(a2, b1, acc[2][1]);
            acc[3][0] = fma2(a3, b0, acc[3][0]); acc[3][1] = fma2(a3, b1, acc[3][1]);
        }
        __syncthreads();
    }

#pragma unroll
    for (int i = 0; i < 4; i++) {
        int r  = row0 + tm * 4 + i;
        int t  = r & (T_ - 1);
        int bb = r >> 10;
#pragma unroll
        for (int j = 0; j < 2; j++) {
            float2 v = unpack2(acc[i][j]);
            int c0c = col0 + tn * 4 + j * 2;
            g_z0t[((size_t)t * G4H + c0c + 0) * B_ + bb] = v.x + bias[c0c + 0];
            g_z0t[((size_t)t * G4H + c0c + 1) * B_ + bb] = v.y + bias[c0c + 1];
        }
    }
}

// ---------------- recurrence ----------------
// Block bx owns h columns [bx*4, bx*4+4). Thread: b = tid&31, nl = tid>>5.
// Dynamic smem: Whs2[H*8] u64 (32KB, interleaved (wi,wf),(wg,wo) pairs)
//             | hstage[H*B] float (64KB)  => 96KB.
__global__ void __launch_bounds__(NT, 1) lstm_rec(const float* __restrict__ c0,
                                                  const float* __restrict__ Wh,
                                                  float* __restrict__ out) {
    extern __shared__ unsigned char dsm[];
    unsigned long long* Whs2 = (unsigned long long*)dsm;   // [k*8 + nl*2 + {0,1}]
    float* hstage = (float*)(Whs2 + H_ * 8);               // [k][b]

    const int tid  = threadIdx.x;
    const int b    = tid & 31;
    const int nl   = tid >> 5;                   // 0..3
    const int ncol = blockIdx.x * 4 + nl;

    // Stage Wh slice once: (wi,wf) and (wg,wo) f32x2 pairs, 16B-aligned per (k,nl).
    for (int idx = tid; idx < H_ * 4; idx += NT) {
        int k  = idx >> 2;
        int n2 = idx & 3;
        int cb = blockIdx.x * 4 + n2;
        float wi = Wh[(size_t)k * G4H + 0 * H_ + cb];
        float wf = Wh[(size_t)k * G4H + 1 * H_ + cb];
        float wg = Wh[(size_t)k * G4H + 2 * H_ + cb];
        float wo = Wh[(size_t)k * G4H + 3 * H_ + cb];
        Whs2[k * 8 + n2 * 2 + 0] = pack2(wi, wf);
        Whs2[k * 8 + n2 * 2 + 1] = pack2(wg, wo);
    }

    float c = c0[(size_t)b * H_ + ncol];

    float* c_fin = out;
    float* h_fin = out + B_ * H_;
    float* hist  = out + 2 * B_ * H_;            // [b][t][h]

    const unsigned long long* Wp = Whs2 + nl * 2;
    const int rot = (blockIdx.x * 5) & 31;       // stagger L2 hotspot
    const int grp = blockIdx.x >> 3;             // 16 groups of 8 blocks

    __syncthreads();

    for (int t = 0; t < T_; t++) {
        const float4* __restrict__ hsrc4 = (const float4*)g_hT[t & 1];
        float* hdst = g_hT[(t + 1) & 1];
        float4* dst4 = (float4*)hstage;

        // ---- z prefetch (overlaps the stage) ----
        size_t zbase = ((size_t)t * G4H + ncol) * B_ + b;
        float z0 = __ldcs(&g_z0t[zbase + (size_t)0 * H_ * B_]);
        float z1 = __ldcs(&g_z0t[zbase + (size_t)1 * H_ * B_]);
        float z2 = __ldcs(&g_z0t[zbase + (size_t)2 * H_ * B_]);
        float z3 = __ldcs(&g_z0t[zbase + (size_t)3 * H_ * B_]);

        // ---- stage h (64KB) via ld.global.cg, 4 chunks of MLP=8, staggered ----
#pragma unroll
        for (int cch = 0; cch < 4; cch++) {
            int i0 = ((cch * 8 + 0) + rot) & 31;
            int i1 = ((cch * 8 + 1) + rot) & 31;
            int i2 = ((cch * 8 + 2) + rot) & 31;
            int i3 = ((cch * 8 + 3) + rot) & 31;
            int i4 = ((cch * 8 + 4) + rot) & 31;
            int i5 = ((cch * 8 + 5) + rot) & 31;
            int i6 = ((cch * 8 + 6) + rot) & 31;
            int i7 = ((cch * 8 + 7) + rot) & 31;
            float4 r0 = __ldcg(&hsrc4[tid + NT * i0]);
            float4 r1 = __ldcg(&hsrc4[tid + NT * i1]);
            float4 r2 = __ldcg(&hsrc4[tid + NT * i2]);
            float4 r3 = __ldcg(&hsrc4[tid + NT * i3]);
            float4 r4 = __ldcg(&hsrc4[tid + NT * i4]);
            float4 r5 = __ldcg(&hsrc4[tid + NT * i5]);
            float4 r6 = __ldcg(&hsrc4[tid + NT * i6]);
            float4 r7 = __ldcg(&hsrc4[tid + NT * i7]);
            dst4[tid + NT * i0] = r0;
            dst4[tid + NT * i1] = r1;
            dst4[tid + NT * i2] = r2;
            dst4[tid + NT * i3] = r3;
            dst4[tid + NT * i4] = r4;
            dst4[tid + NT * i5] = r5;
            dst4[tid + NT * i6] = r6;
            dst4[tid + NT * i7] = r7;
        }
        __syncthreads();

        // ---- gate pre-activations: f32x2, 2 partial accumulators per pair ----
        unsigned long long aif0 = pack2(z0, z1), aif1 = 0;
        unsigned long long ago0 = pack2(z2, z3), ago1 = 0;
#pragma unroll 8
        for (int k = 0; k < H_; k += 2) {
            float hv0 = hstage[(k + 0) * B_ + b];
            float hv1 = hstage[(k + 1) * B_ + b];
            unsigned long long hh0 = pack2(hv0, hv0);
            unsigned long long hh1 = pack2(hv1, hv1);
            ulonglong2 w0 = *(const ulonglong2*)(Wp + (size_t)(k + 0) * 8);
            ulonglong2 w1 = *(const ulonglong2*)(Wp + (size_t)(k + 1) * 8);
            aif0 = fma2(hh0, w0.x, aif0);
            ago0 = fma2(hh0, w0.y, ago0);
            aif1 = fma2(hh1, w1.x, aif1);
            ago1 = fma2(hh1, w1.y, ago1);
        }
        float2 zif = unpack2(add2(aif0, aif1));
        float2 zgo = unpack2(add2(ago0, ago1));

        float ig = 1.f / (1.f + __expf(-zif.x));
        float fg = 1.f / (1.f + __expf(-zif.y));
        float gg = tanhf(zgo.x);
        float og = 1.f / (1.f + __expf(-zgo.y));
        c = fg * c + ig * gg;
        float h = og * tanhf(c);

        __stcg(&hdst[ncol * B_ + b], h);                   // publish via L2
        hist[((size_t)b * T_ + t) * H_ + ncol] = h;

        if (t == T_ - 1) {
            c_fin[b * H_ + ncol] = c;
            h_fin[b * H_ + ncol] = h;
        }

        // ---- monotonic hierarchical grid barrier ----
        __threadfence();              // order h publish before arrive
        __syncthreads();              // all lanes done with hstage, too
        if (tid == 0) {
            unsigned target = (unsigned)(t + 1);
            unsigned old = atomicAdd(&g_grp[grp * 32], 1);
            if (old == 8u * target - 1u) {
                unsigned r = atomicAdd(&g_root, 1);
                if (r == 16u * target - 1u) g_sense = target;
            }
            while (g_sense < target) { }
        }
        __syncthreads();
        // no consumer threadfence: all cross-step reads bypass L1 (.cg/.volatile)
    }
}

// ---------------- launch ----------------
extern "C" void kernel_launch(void* const* d_in, const int* in_sizes, int n_in,
                              void* d_out, int out_size) {
    const float* x    = (const float*)d_in[0];
    const float* h0   = (const float*)d_in[1];
    const float* c0   = (const float*)d_in[2];
    const float* Wi   = (const float*)d_in[3];
    const float* Wh   = (const float*)d_in[4];
    const float* bias = (const float*)d_in[5];
    float* out = (float*)d_out;

    const int rec_smem = H_ * 8 * 8 + H_ * B_ * 4;   // 32KB + 64KB = 98304
    cudaFuncSetAttribute(lstm_rec, cudaFuncAttributeMaxDynamicSharedMemorySize,
                         rec_smem);

    dim3 ggrid(G4H / 64, (B_ * T_) / 64);
    gemm_xwi<<<ggrid, 256>>>(x, Wi, bias, h0);

    lstm_rec<<<NB, NT, rec_smem>>>(c0, Wh, out);
}